// round 1
// baseline (speedup 1.0000x reference)
#include <cuda_runtime.h>
#include <math.h>

// Problem constants
#define TOTAL_ELEMS (16*256*1024)   // 4194304 elements of z
#define N_CODES 4096
#define E_DIM   256
#define N_VECS  16384               // 16 * 32 * 32
#define DECAYF  0.99f
#define OMDF    0.01f               // 1 - decay
#define BETAF   0.25f
#define EPSF    1e-5f

// Output layout: flattened tuple, float32
// (loss, z_q_out, perplexity, idx, new_embedding, new_cluster_size, new_embed_avg)
#define OFF_LOSS 0
#define OFF_ZQ   1
#define OFF_PERP (1 + TOTAL_ELEMS)
#define OFF_IDX  (2 + TOTAL_ELEMS)
#define OFF_EMB  (2 + TOTAL_ELEMS + N_VECS)
#define OFF_CS   (OFF_EMB + N_CODES*E_DIM)
#define OFF_EA   (OFF_CS + N_CODES)

// Scratch (no allocation allowed -> device globals)
__device__ float g_enorm[N_CODES];            // 0.5*||e_j||^2
__device__ float g_embT[E_DIM * N_CODES];     // embedding transposed [k][code]
__device__ int   g_idx[N_VECS];
__device__ float g_enc_sum[N_CODES];
__device__ float g_embed_sum[N_CODES * E_DIM];
__device__ float g_loss;
__device__ float g_n;

// ---------------------------------------------------------------------------
__global__ void k_zero() {
    int t = blockIdx.x * blockDim.x + threadIdx.x;
    int nt = gridDim.x * blockDim.x;
    for (int i = t; i < N_CODES * E_DIM; i += nt) g_embed_sum[i] = 0.f;
    for (int i = t; i < N_CODES; i += nt) g_enc_sum[i] = 0.f;
    if (t == 0) g_loss = 0.f;
}

// ---------------------------------------------------------------------------
// 0.5 * ||e_j||^2 , one warp per code row
__global__ void k_enorm(const float* __restrict__ emb) {
    int warp = (blockIdx.x * blockDim.x + threadIdx.x) >> 5;
    int lane = threadIdx.x & 31;
    if (warp >= N_CODES) return;
    const float* r = emb + warp * E_DIM;
    float s = 0.f;
    #pragma unroll
    for (int c = 0; c < E_DIM; c += 32) {
        float v = r[c + lane];
        s += v * v;
    }
    #pragma unroll
    for (int o = 16; o; o >>= 1) s += __shfl_down_sync(0xffffffffu, s, o);
    if (lane == 0) g_enorm[warp] = 0.5f * s;
}

// ---------------------------------------------------------------------------
// Transpose embedding (4096 x 256) -> embT (256 x 4096) so B-tile loads in the
// GEMM are coalesced and the smem stage is conflict-free.
__global__ void k_transpose(const float* __restrict__ emb) {
    __shared__ float t[32][33];
    int x  = blockIdx.x * 32 + threadIdx.x;   // k   (blockIdx.x 0..7)
    int y0 = blockIdx.y * 32;                 // code (blockIdx.y 0..127)
    #pragma unroll
    for (int i = 0; i < 32; i += 8)
        t[threadIdx.y + i][threadIdx.x] = emb[(y0 + threadIdx.y + i) * E_DIM + x];
    __syncthreads();
    int c  = y0 + threadIdx.x;                // code out
    int k0 = blockIdx.x * 32;
    #pragma unroll
    for (int i = 0; i < 32; i += 8)
        g_embT[(k0 + threadIdx.y + i) * N_CODES + c] = t[threadIdx.x][threadIdx.y + i];
}

// ---------------------------------------------------------------------------
// Fused score GEMM + argmax.
// Block: 32 rows of zf x all 4096 codes. 256 threads as (tx=16, ty=16),
// each thread computes a 2x4 accumulator tile.
// score(m, j) = zf[m] . e_j - 0.5*||e_j||^2  ; argmax score == argmin dist.
__global__ __launch_bounds__(256) void k_score(const float* __restrict__ z,
                                               float* __restrict__ dout) {
    __shared__ float As[E_DIM * 32];   // [k][m], 8192 floats = 32KB
    __shared__ float Bs[32 * 64];      // [k][code], 2048 floats = 8KB
    __shared__ float Ens[64];

    int tid = threadIdx.x;
    int tx = tid & 15, ty = tid >> 4;
    int m0 = blockIdx.x * 32;          // 512 blocks
    int b  = m0 >> 10;                 // batch (1024 pixels per image)
    int p0 = m0 & 1023;
    const float* zb = z + (size_t)b * (E_DIM * 1024) + p0;

    // Fill As: zf[m][k] = z[b, k, p0+m]; per-warp reads are 128B contiguous.
    #pragma unroll
    for (int i = 0; i < 32; ++i) {
        int li = tid + i * 256;        // li = k*32 + m
        int k = li >> 5, m = li & 31;
        As[li] = zb[k * 1024 + m];
    }

    float bestv[2] = {-1e30f, -1e30f};
    int   besti[2] = {0, 0};

    for (int ct = 0; ct < 64; ++ct) {
        int c0 = ct << 6;
        __syncthreads();                   // protects Ens (reads of previous iter done)
        if (tid < 64) Ens[tid] = g_enorm[c0 + tid];

        float acc[2][4] = {{0.f,0.f,0.f,0.f},{0.f,0.f,0.f,0.f}};
        for (int kt = 0; kt < 8; ++kt) {
            __syncthreads();
            // Stage Bs: 32 k x 64 codes from embT (coalesced, conflict-free)
            #pragma unroll
            for (int it = 0; it < 2; ++it) {
                int li = tid + it * 256;       // 0..511 float4 slots
                int kk = li >> 4;
                int cc = (li & 15) << 2;
                float4 v = *(const float4*)(g_embT + (size_t)(kt*32 + kk) * N_CODES + c0 + cc);
                *(float4*)(Bs + kk * 64 + cc) = v;
            }
            __syncthreads();
            #pragma unroll
            for (int k = 0; k < 32; ++k) {
                float2 a  = *(const float2*)(As + (kt*32 + k) * 32 + ty * 2);
                float4 bb = *(const float4*)(Bs + k * 64 + tx * 4);
                acc[0][0] += a.x * bb.x; acc[0][1] += a.x * bb.y;
                acc[0][2] += a.x * bb.z; acc[0][3] += a.x * bb.w;
                acc[1][0] += a.y * bb.x; acc[1][1] += a.y * bb.y;
                acc[1][2] += a.y * bb.z; acc[1][3] += a.y * bb.w;
            }
        }
        // Running argmax (strict > keeps the first/lowest index on ties,
        // matching jnp.argmin's first-min semantics within this thread's codes)
        #pragma unroll
        for (int i = 0; i < 2; ++i) {
            #pragma unroll
            for (int j = 0; j < 4; ++j) {
                int code = c0 + tx * 4 + j;
                float v = acc[i][j] - Ens[tx * 4 + j];
                if (v > bestv[i]) { bestv[i] = v; besti[i] = code; }
            }
        }
    }
    __syncthreads();
    // Cross-thread reduction per row; reuse Bs as scratch.
    float* redV = Bs;                  // 32*16 floats
    int*   redI = (int*)(Bs + 512);    // 32*16 ints
    #pragma unroll
    for (int i = 0; i < 2; ++i) {
        int row = ty * 2 + i;
        redV[row * 16 + tx] = bestv[i];
        redI[row * 16 + tx] = besti[i];
    }
    __syncthreads();
    if (tid < 32) {
        float bv = redV[tid * 16];
        int   bi = redI[tid * 16];
        #pragma unroll
        for (int t = 1; t < 16; ++t) {
            float v = redV[tid * 16 + t];
            int  id = redI[tid * 16 + t];
            if (v > bv || (v == bv && id < bi)) { bv = v; bi = id; }
        }
        int n = m0 + tid;
        g_idx[n] = bi;
        dout[OFF_IDX + n] = (float)bi;
    }
}

// ---------------------------------------------------------------------------
// Gather codebook rows into z_q_out (B,C,H,W order), commitment loss,
// and segment sums (counts + per-code vector sums) via global RED.ADD.
__global__ void k_gather(const float* __restrict__ z, const float* __restrict__ emb,
                         float* __restrict__ dout) {
    __shared__ float sred[256];
    int t  = blockIdx.x * blockDim.x + threadIdx.x;
    int nt = gridDim.x * blockDim.x;
    float ls = 0.f;
    for (int e = t; e < TOTAL_ELEMS; e += nt) {
        int p  = e & 1023;
        int c  = (e >> 10) & 255;
        int bb = e >> 18;
        int n  = (bb << 10) + p;
        int code = g_idx[n];
        float zv = z[e];
        float ev = __ldg(emb + (size_t)code * E_DIM + c);
        dout[OFF_ZQ + e] = ev;                    // z_q_st == z_q numerically (~1 ulp)
        float d = ev - zv;
        ls += d * d;
        atomicAdd(g_embed_sum + (size_t)code * E_DIM + c, zv);
        if (c == 0) atomicAdd(g_enc_sum + code, 1.0f);
    }
    sred[threadIdx.x] = ls;
    __syncthreads();
    for (int s = 128; s; s >>= 1) {
        if (threadIdx.x < s) sred[threadIdx.x] += sred[threadIdx.x + s];
        __syncthreads();
    }
    if (threadIdx.x == 0) atomicAdd(&g_loss, sred[0]);
}

// ---------------------------------------------------------------------------
// new_cluster_size, n = sum(ncs), perplexity, loss scalar. Single block.
__global__ void k_fin1(const float* __restrict__ cs, float* __restrict__ dout) {
    __shared__ float sn[1024];
    __shared__ float sp[1024];
    int t = threadIdx.x;
    float ln = 0.f, lp = 0.f;
    for (int j = t; j < N_CODES; j += 1024) {
        float es  = g_enc_sum[j];
        float ncs = cs[j] * DECAYF + OMDF * es;
        dout[OFF_CS + j] = ncs;
        ln += ncs;
        float pr = es * (1.0f / (float)N_VECS);
        lp += pr * logf(pr + 1e-10f);
    }
    sn[t] = ln; sp[t] = lp;
    __syncthreads();
    for (int s = 512; s; s >>= 1) {
        if (t < s) { sn[t] += sn[t + s]; sp[t] += sp[t + s]; }
        __syncthreads();
    }
    if (t == 0) {
        g_n = sn[0];
        dout[OFF_PERP] = expf(-sp[0]);
        dout[OFF_LOSS] = g_loss * (BETAF / (float)TOTAL_ELEMS);
    }
}

// ---------------------------------------------------------------------------
// new_embed_avg and new_embedding (needs n from k_fin1).
__global__ void k_fin2(const float* __restrict__ ea, float* __restrict__ dout) {
    int i = blockIdx.x * blockDim.x + threadIdx.x;
    if (i >= N_CODES * E_DIM) return;
    int code = i >> 8;
    float nea = ea[i] * DECAYF + OMDF * g_embed_sum[i];
    dout[OFF_EA + i] = nea;
    float ncs = dout[OFF_CS + code];      // written by k_fin1 (sequential)
    float n = g_n;
    float sm = (ncs + EPSF) / (n + (float)N_CODES * EPSF) * n;
    dout[OFF_EMB + i] = nea / sm;
}

// ---------------------------------------------------------------------------
extern "C" void kernel_launch(void* const* d_in, const int* in_sizes, int n_in,
                              void* d_out, int out_size) {
    const float* z   = (const float*)d_in[0];   // (16,256,32,32)
    const float* emb = (const float*)d_in[1];   // (4096,256)
    const float* cs  = (const float*)d_in[2];   // (4096,)
    const float* ea  = (const float*)d_in[3];   // (4096,256)
    float* out = (float*)d_out;

    k_zero<<<1024, 512>>>();
    k_enorm<<<512, 256>>>(emb);
    k_transpose<<<dim3(8, 128), dim3(32, 8)>>>(emb);
    k_score<<<512, 256>>>(z, out);
    k_gather<<<4096, 256>>>(z, emb, out);
    k_fin1<<<1, 1024>>>(cs, out);
    k_fin2<<<4096, 256>>>(ea, out);
}

// round 2
// speedup vs baseline: 1.2080x; 1.2080x over previous
#include <cuda_runtime.h>
#include <math.h>

// Problem constants
#define TOTAL_ELEMS (16*256*1024)   // 4194304 elements of z
#define N_CODES 4096
#define E_DIM   256
#define N_VECS  16384               // 16 * 32 * 32
#define DECAYF  0.99f
#define OMDF    0.01f               // 1 - decay
#define BETAF   0.25f
#define EPSF    1e-5f

// Output layout: flattened tuple, float32
#define OFF_LOSS 0
#define OFF_ZQ   1
#define OFF_PERP (1 + TOTAL_ELEMS)
#define OFF_IDX  (2 + TOTAL_ELEMS)
#define OFF_EMB  (2 + TOTAL_ELEMS + N_VECS)
#define OFF_CS   (OFF_EMB + N_CODES*E_DIM)
#define OFF_EA   (OFF_CS + N_CODES)

// Scratch (no allocation allowed -> device globals)
__device__ float g_enorm[N_CODES];            // 0.5*||e_j||^2
__device__ float g_embT[E_DIM * N_CODES];     // embedding transposed [k][code]
__device__ int   g_idx[N_VECS];
__device__ float g_enc_sum[N_CODES];
__device__ float g_embed_sum[N_CODES * E_DIM];
__device__ float g_loss;
__device__ float g_n;

// ---------------------------------------------------------------------------
__global__ void k_zero() {
    int t = blockIdx.x * blockDim.x + threadIdx.x;
    int nt = gridDim.x * blockDim.x;
    for (int i = t; i < N_CODES * E_DIM; i += nt) g_embed_sum[i] = 0.f;
    for (int i = t; i < N_CODES; i += nt) g_enc_sum[i] = 0.f;
    if (t == 0) g_loss = 0.f;
}

// ---------------------------------------------------------------------------
// 0.5 * ||e_j||^2 , one warp per code row
__global__ void k_enorm(const float* __restrict__ emb) {
    int warp = (blockIdx.x * blockDim.x + threadIdx.x) >> 5;
    int lane = threadIdx.x & 31;
    if (warp >= N_CODES) return;
    const float* r = emb + warp * E_DIM;
    float s = 0.f;
    #pragma unroll
    for (int c = 0; c < E_DIM; c += 32) {
        float v = r[c + lane];
        s += v * v;
    }
    #pragma unroll
    for (int o = 16; o; o >>= 1) s += __shfl_down_sync(0xffffffffu, s, o);
    if (lane == 0) g_enorm[warp] = 0.5f * s;
}

// ---------------------------------------------------------------------------
// Transpose embedding (4096 x 256) -> embT (256 x 4096)
__global__ void k_transpose(const float* __restrict__ emb) {
    __shared__ float t[32][33];
    int x  = blockIdx.x * 32 + threadIdx.x;   // k
    int y0 = blockIdx.y * 32;                 // code
    #pragma unroll
    for (int i = 0; i < 32; i += 8)
        t[threadIdx.y + i][threadIdx.x] = emb[(y0 + threadIdx.y + i) * E_DIM + x];
    __syncthreads();
    int c  = y0 + threadIdx.x;
    int k0 = blockIdx.x * 32;
    #pragma unroll
    for (int i = 0; i < 32; i += 8)
        g_embT[(k0 + threadIdx.y + i) * N_CODES + c] = t[threadIdx.x][threadIdx.y + i];
}

// ---------------------------------------------------------------------------
// Fused score GEMM + argmax. Block: 64 rows x all 4096 codes, 256 threads,
// per-thread 4x8 accumulator tile. A-panel (K=256 x M=64, 64KB) resident in
// smem; B staged in 32k x 128c chunks with register prefetch.
// score(m, j) = zf[m].e_j - 0.5*||e_j||^2 ; argmax score == argmin dist.
__global__ __launch_bounds__(256) void k_score(const float* __restrict__ z,
                                               float* __restrict__ dout) {
    extern __shared__ float smf[];
    float* As  = smf;                       // [256][64]  64KB
    float* Bs  = smf + E_DIM * 64;          // [32][128]  16KB
    float* Ens = smf + E_DIM * 64 + 32*128; // [128]

    int tid = threadIdx.x;
    int tx = tid & 15, ty = tid >> 4;
    int m0 = blockIdx.x * 64;               // 256 blocks
    int b  = m0 >> 10;
    int p0 = m0 & 1023;
    const float* zb = z + (size_t)b * (E_DIM * 1024) + p0;

    // Load full A panel: As[k][m] = z[b, k, p0+m]; coalesced float4.
    #pragma unroll
    for (int it = 0; it < 16; ++it) {
        int li = tid + it * 256;            // 4096 float4 slots
        int k  = li >> 4;
        int mq = (li & 15) << 2;
        float4 v = *(const float4*)(zb + k * 1024 + mq);
        *(float4*)(As + k * 64 + mq) = v;
    }

    float bestv[4] = {-1e30f, -1e30f, -1e30f, -1e30f};
    int   besti[4] = {0, 0, 0, 0};

    // Prefetch first B chunk into registers.
    int kks[4], ccs[4];
    float4 pf[4];
    #pragma unroll
    for (int it = 0; it < 4; ++it) {
        int li = tid + it * 256;            // 1024 float4 slots
        kks[it] = li >> 5;                  // k within chunk (0..31)
        ccs[it] = (li & 31) << 2;           // col within chunk (0..124)
        pf[it] = *(const float4*)(g_embT + (size_t)kks[it] * N_CODES + ccs[it]);
    }

    for (int ct = 0; ct < 32; ++ct) {
        int c0 = ct << 7;
        __syncthreads();                    // prior readers of Ens/Bs done
        if (tid < 128) Ens[tid] = g_enorm[c0 + tid];

        float acc[4][8];
        #pragma unroll
        for (int i = 0; i < 4; ++i)
            #pragma unroll
            for (int j = 0; j < 8; ++j) acc[i][j] = 0.f;

        for (int kt = 0; kt < 8; ++kt) {
            if (kt) __syncthreads();        // prior compute done reading Bs
            #pragma unroll
            for (int it = 0; it < 4; ++it)
                *(float4*)(Bs + kks[it] * 128 + ccs[it]) = pf[it];
            __syncthreads();

            // Prefetch next chunk (hidden behind compute).
            int q = ct * 8 + kt + 1;
            if (q < 256) {
                int ctn = q >> 3, ktn = q & 7;
                #pragma unroll
                for (int it = 0; it < 4; ++it)
                    pf[it] = *(const float4*)(g_embT
                        + (size_t)((ktn << 5) + kks[it]) * N_CODES
                        + (ctn << 7) + ccs[it]);
            }

            #pragma unroll 4
            for (int k = 0; k < 32; ++k) {
                float4 av = *(const float4*)(As + (((kt << 5) + k) << 6) + (ty << 2));
                float4 b0 = *(const float4*)(Bs + (k << 7) + (tx << 3));
                float4 b1 = *(const float4*)(Bs + (k << 7) + (tx << 3) + 4);
                float aa[4] = {av.x, av.y, av.z, av.w};
                float bb[8] = {b0.x, b0.y, b0.z, b0.w, b1.x, b1.y, b1.z, b1.w};
                #pragma unroll
                for (int i = 0; i < 4; ++i)
                    #pragma unroll
                    for (int j = 0; j < 8; ++j)
                        acc[i][j] = fmaf(aa[i], bb[j], acc[i][j]);
            }
        }
        // Running argmax (strict > keeps lowest index; codes ascend over ct/j).
        #pragma unroll
        for (int i = 0; i < 4; ++i) {
            #pragma unroll
            for (int j = 0; j < 8; ++j) {
                float v = acc[i][j] - Ens[(tx << 3) + j];
                if (v > bestv[i]) { bestv[i] = v; besti[i] = c0 + (tx << 3) + j; }
            }
        }
    }
    __syncthreads();
    // Cross-thread reduction per row; reuse Bs as scratch.
    float* redV = Bs;                       // 64*16 floats
    int*   redI = (int*)(Bs + 1024);        // 64*16 ints
    #pragma unroll
    for (int i = 0; i < 4; ++i) {
        int row = (ty << 2) + i;
        redV[row * 16 + tx] = bestv[i];
        redI[row * 16 + tx] = besti[i];
    }
    __syncthreads();
    if (tid < 64) {
        float bv = redV[tid * 16];
        int   bi = redI[tid * 16];
        #pragma unroll
        for (int t = 1; t < 16; ++t) {
            float v = redV[tid * 16 + t];
            int  id = redI[tid * 16 + t];
            if (v > bv || (v == bv && id < bi)) { bv = v; bi = id; }
        }
        int n = m0 + tid;
        g_idx[n] = bi;
        dout[OFF_IDX + n] = (float)bi;
    }
}

// ---------------------------------------------------------------------------
// Gather codebook rows into z_q_out, commitment loss, segment sums.
__global__ void k_gather(const float* __restrict__ z, const float* __restrict__ emb,
                         float* __restrict__ dout) {
    __shared__ float sred[256];
    int t  = blockIdx.x * blockDim.x + threadIdx.x;
    int nt = gridDim.x * blockDim.x;
    float ls = 0.f;
    for (int e = t; e < TOTAL_ELEMS; e += nt) {
        int p  = e & 1023;
        int c  = (e >> 10) & 255;
        int bb = e >> 18;
        int n  = (bb << 10) + p;
        int code = g_idx[n];
        float zv = z[e];
        float ev = __ldg(emb + (size_t)code * E_DIM + c);
        dout[OFF_ZQ + e] = ev;              // z_q_st == z_q numerically
        float d = ev - zv;
        ls += d * d;
        atomicAdd(g_embed_sum + (size_t)code * E_DIM + c, zv);
        if (c == 0) atomicAdd(g_enc_sum + code, 1.0f);
    }
    sred[threadIdx.x] = ls;
    __syncthreads();
    for (int s = 128; s; s >>= 1) {
        if (threadIdx.x < s) sred[threadIdx.x] += sred[threadIdx.x + s];
        __syncthreads();
    }
    if (threadIdx.x == 0) atomicAdd(&g_loss, sred[0]);
}

// ---------------------------------------------------------------------------
__global__ void k_fin1(const float* __restrict__ cs, float* __restrict__ dout) {
    __shared__ float sn[1024];
    __shared__ float sp[1024];
    int t = threadIdx.x;
    float ln = 0.f, lp = 0.f;
    for (int j = t; j < N_CODES; j += 1024) {
        float es  = g_enc_sum[j];
        float ncs = cs[j] * DECAYF + OMDF * es;
        dout[OFF_CS + j] = ncs;
        ln += ncs;
        float pr = es * (1.0f / (float)N_VECS);
        lp += pr * logf(pr + 1e-10f);
    }
    sn[t] = ln; sp[t] = lp;
    __syncthreads();
    for (int s = 512; s; s >>= 1) {
        if (t < s) { sn[t] += sn[t + s]; sp[t] += sp[t + s]; }
        __syncthreads();
    }
    if (t == 0) {
        g_n = sn[0];
        dout[OFF_PERP] = expf(-sp[0]);
        dout[OFF_LOSS] = g_loss * (BETAF / (float)TOTAL_ELEMS);
    }
}

// ---------------------------------------------------------------------------
__global__ void k_fin2(const float* __restrict__ ea, float* __restrict__ dout) {
    int i = blockIdx.x * blockDim.x + threadIdx.x;
    if (i >= N_CODES * E_DIM) return;
    int code = i >> 8;
    float nea = ea[i] * DECAYF + OMDF * g_embed_sum[i];
    dout[OFF_EA + i] = nea;
    float ncs = dout[OFF_CS + code];
    float n = g_n;
    float sm = (ncs + EPSF) / (n + (float)N_CODES * EPSF) * n;
    dout[OFF_EMB + i] = nea / sm;
}

// ---------------------------------------------------------------------------
extern "C" void kernel_launch(void* const* d_in, const int* in_sizes, int n_in,
                              void* d_out, int out_size) {
    const float* z   = (const float*)d_in[0];   // (16,256,32,32)
    const float* emb = (const float*)d_in[1];   // (4096,256)
    const float* cs  = (const float*)d_in[2];   // (4096,)
    const float* ea  = (const float*)d_in[3];   // (4096,256)
    float* out = (float*)d_out;

    const int SMEM_SCORE = (E_DIM * 64 + 32 * 128 + 128) * (int)sizeof(float); // 82432
    cudaFuncSetAttribute(k_score, cudaFuncAttributeMaxDynamicSharedMemorySize, SMEM_SCORE);

    k_zero<<<1024, 512>>>();
    k_enorm<<<512, 256>>>(emb);
    k_transpose<<<dim3(8, 128), dim3(32, 8)>>>(emb);
    k_score<<<256, 256, SMEM_SCORE>>>(z, out);
    k_gather<<<4096, 256>>>(z, emb, out);
    k_fin1<<<1, 1024>>>(cs, out);
    k_fin2<<<4096, 256>>>(ea, out);
}

// round 6
// speedup vs baseline: 2.0760x; 1.7185x over previous
#include <cuda_runtime.h>
#include <cuda_bf16.h>
#include <math.h>
#include <stdint.h>

// ---------------------------------------------------------------- constants
#define TOTAL_ELEMS (16*256*1024)
#define N_CODES 4096
#define E_DIM   256
#define N_VECS  16384
#define DECAYF  0.99f
#define OMDF    0.01f
#define BETAF   0.25f
#define EPSF    1e-5f

#define OFF_LOSS 0
#define OFF_ZQ   1
#define OFF_PERP (1 + TOTAL_ELEMS)
#define OFF_IDX  (2 + TOTAL_ELEMS)
#define OFF_EMB  (2 + TOTAL_ELEMS + N_VECS)
#define OFF_CS   (OFF_EMB + N_CODES*E_DIM)
#define OFF_EA   (OFF_CS + N_CODES)

// GEMM geometry: block = 128 rows x 256-code chunks (16 chunks)
// 8 warps: warp_m in {0,1}, warp_n in {0..3}. Warp tile 64x64.
// Within-chunk tile order is kt-major: tile = 3*kt + sb  (fixes A2 staleness).
#define M_BLK 128
#define N_CHUNK 256
#define N_CHUNKS 16
#define TILES_PER_CHUNK 24          // 8 k-tiles x 3 B-splits
#define N_TILES (N_CHUNKS * TILES_PER_CHUNK)   // 384

// smem layout (bytes from base)
#define A_STRIDE 528                // 256 bf16 = 512B + 16 pad (ldmatrix conflict-free)
#define SOFF_A    0                 // 2 splits x 128 x 528 = 135168
#define SOFF_B    135168            // 2 bufs x 256*80 = 40960
#define SOFF_A2   176128            // 2 bufs x 128*80 = 20480
#define SOFF_ENS  196608            // 2 bufs x 1024
#define SMEM_TOTAL 198656

// ---------------------------------------------------------------- scratch
__device__ __align__(128) __nv_bfloat16 g_zs[3][(size_t)N_VECS * E_DIM];
__device__ __align__(128) __nv_bfloat16 g_es[3][(size_t)N_CODES * E_DIM];
__device__ __align__(128) float g_enorm[N_CODES];
__device__ __align__(128) int   g_idx[N_VECS];
__device__ __align__(128) float g_enc_sum[N_CODES];
__device__ __align__(128) float g_embed_sum[N_CODES * E_DIM];
__device__ float g_loss;
__device__ float g_n;

// ---------------------------------------------------------------- asm helpers
__device__ __forceinline__ uint32_t smem_u32(const void* p) {
    uint32_t a;
    asm("{ .reg .u64 t; cvta.to.shared.u64 t, %1; cvt.u32.u64 %0, t; }" : "=r"(a) : "l"(p));
    return a;
}
#define CP16(dst, src)   asm volatile("cp.async.cg.shared.global [%0], [%1], 16;" :: "r"(dst), "l"(src) : "memory")
#define CP_COMMIT()      asm volatile("cp.async.commit_group;" ::: "memory")
#define CP_WAIT1()       asm volatile("cp.async.wait_group 1;" ::: "memory")
#define CP_WAIT0()       asm volatile("cp.async.wait_group 0;" ::: "memory")

#define LDSM_X4(r, addr) asm volatile( \
    "ldmatrix.sync.aligned.m8n8.x4.shared.b16 {%0,%1,%2,%3}, [%4];" \
    : "=r"((r)[0]),"=r"((r)[1]),"=r"((r)[2]),"=r"((r)[3]) : "r"(addr))
#define LDSM_X2(r, addr) asm volatile( \
    "ldmatrix.sync.aligned.m8n8.x2.shared.b16 {%0,%1}, [%2];" \
    : "=r"((r)[0]),"=r"((r)[1]) : "r"(addr))

#define MMA16816(c, a, b) asm volatile( \
    "mma.sync.aligned.m16n8k16.row.col.f32.bf16.bf16.f32 " \
    "{%0,%1,%2,%3}, {%4,%5,%6,%7}, {%8,%9}, {%0,%1,%2,%3};" \
    : "+f"((c)[0]),"+f"((c)[1]),"+f"((c)[2]),"+f"((c)[3]) \
    : "r"((a)[0]),"r"((a)[1]),"r"((a)[2]),"r"((a)[3]), "r"((b)[0]),"r"((b)[1]))

// ---------------------------------------------------------------- prep kernels
__global__ void k_zero() {
    int t = blockIdx.x * blockDim.x + threadIdx.x;
    int nt = gridDim.x * blockDim.x;
    for (int i = t; i < N_CODES * E_DIM; i += nt) g_embed_sum[i] = 0.f;
    for (int i = t; i < N_CODES; i += nt) g_enc_sum[i] = 0.f;
    if (t == 0) g_loss = 0.f;
}

__global__ void k_enorm(const float* __restrict__ emb) {
    int warp = (blockIdx.x * blockDim.x + threadIdx.x) >> 5;
    int lane = threadIdx.x & 31;
    if (warp >= N_CODES) return;
    const float* r = emb + warp * E_DIM;
    float s = 0.f;
    #pragma unroll
    for (int c = 0; c < E_DIM; c += 32) { float v = r[c + lane]; s += v * v; }
    #pragma unroll
    for (int o = 16; o; o >>= 1) s += __shfl_down_sync(0xffffffffu, s, o);
    if (lane == 0) g_enorm[warp] = 0.5f * s;
}

__device__ __forceinline__ void split3(float v, __nv_bfloat16& h0, __nv_bfloat16& h1, __nv_bfloat16& h2) {
    h0 = __float2bfloat16(v);
    float r1 = v - __bfloat162float(h0);
    h1 = __float2bfloat16(r1);
    float r2 = r1 - __bfloat162float(h1);
    h2 = __float2bfloat16(r2);
}

// z (b, c, p) -> g_zs[s][n = b*1024+p][k = c]
__global__ void k_split_z(const float* __restrict__ z) {
    __shared__ float t[32][33];
    int b  = blockIdx.z;
    int c0 = blockIdx.y * 32;
    int p0 = blockIdx.x * 32;
    #pragma unroll
    for (int i = 0; i < 32; i += 8)
        t[threadIdx.y + i][threadIdx.x] =
            z[((size_t)(b * 256 + c0 + threadIdx.y + i)) * 1024 + p0 + threadIdx.x];
    __syncthreads();
    #pragma unroll
    for (int i = 0; i < 32; i += 8) {
        int n = b * 1024 + p0 + threadIdx.y + i;
        int k = c0 + threadIdx.x;
        float v = t[threadIdx.x][threadIdx.y + i];
        __nv_bfloat16 h0, h1, h2; split3(v, h0, h1, h2);
        size_t o = (size_t)n * E_DIM + k;
        g_zs[0][o] = h0; g_zs[1][o] = h1; g_zs[2][o] = h2;
    }
}

__global__ void k_split_e(const float* __restrict__ emb) {
    int i = blockIdx.x * blockDim.x + threadIdx.x;
    if (i >= N_CODES * E_DIM) return;
    __nv_bfloat16 h0, h1, h2; split3(emb[i], h0, h1, h2);
    g_es[0][i] = h0; g_es[1][i] = h1; g_es[2][i] = h2;
}

// ---------------------------------------------------------------- main HMMA kernel
__global__ __launch_bounds__(256) void k_mma(float* __restrict__ dout) {
    extern __shared__ char smem_raw[];
    const uint32_t SB = smem_u32(smem_raw);
    const int tid  = threadIdx.x;
    const int lane = tid & 31;
    const int wid  = tid >> 5;
    const int warp_m = wid >> 2;        // 0..1
    const int warp_n = wid & 3;         // 0..3
    const int m0 = blockIdx.x * M_BLK;

    // per-thread ldmatrix address components
    const int a_row = warp_m * 64 + ((lane >> 3) & 1) * 8 + (lane & 7);
    const uint32_t a_res_off = (uint32_t)(a_row * A_STRIDE + ((lane >> 4) & 1) * 16);
    const uint32_t a2_off    = (uint32_t)(a_row * 80 + ((lane >> 4) & 1) * 16);
    const int lb = lane & 15;
    const uint32_t b_off = (uint32_t)((warp_n * 64 + (lb & 7)) * 80 + ((lb >> 3) & 1) * 16);

    // ---- issue helper (cp.async). Tile tt: chunk = tt/24, r = tt%24,
    //      kt = r/3 (k-tile of 32), sb_ = r%3 (B split). kt-major order.
    auto issue_tile = [&](int tt) {
        int r24   = tt % TILES_PER_CHUNK;
        int kt    = r24 / 3;
        int sb_   = r24 % 3;
        int chunk = tt / TILES_PER_CHUNK;
        int buf   = tt & 1;
        // B: 256 codes x 32 k of split sb_
        #pragma unroll
        for (int i = 0; i < 4; ++i) {
            int li = tid + i * 256;          // 0..1023
            int code = li >> 2, seg = li & 3;
            const char* src = (const char*)(g_es[sb_]
                + (size_t)(chunk * N_CHUNK + code) * E_DIM + kt * 32 + seg * 8);
            CP16(SB + SOFF_B + buf * 20480 + code * 80 + seg * 16, src);
        }
        if (sb_ == 0) {                      // A2 tile: 128 rows x 32 k (consumed same tile)
            #pragma unroll
            for (int i = 0; i < 2; ++i) {
                int li = tid + i * 256;      // 0..511
                int row = li >> 2, seg = li & 3;
                const char* src = (const char*)(g_zs[2]
                    + (size_t)(m0 + row) * E_DIM + kt * 32 + seg * 8);
                CP16(SB + SOFF_A2 + buf * 10240 + row * 80 + seg * 16, src);
            }
        }
        if (r24 == 0 && tid < 64) {          // ens for this chunk
            const char* src = (const char*)(g_enorm + chunk * N_CHUNK + tid * 4);
            CP16(SB + SOFF_ENS + (chunk & 1) * 1024 + tid * 16, src);
        }
        CP_COMMIT();
    };

    // A panel (splits 0,1) resident
    #pragma unroll
    for (int i = 0; i < 32; ++i) {
        int li = tid + i * 256;              // 0..8191
        int s = li >> 12;
        int rem = li & 4095;
        int row = rem >> 5, seg = rem & 31;
        const char* src = (const char*)(g_zs[s] + (size_t)(m0 + row) * E_DIM + seg * 8);
        CP16(SB + SOFF_A + s * 67584 + row * A_STRIDE + seg * 16, src);
    }
    CP_COMMIT();
    issue_tile(0);
    issue_tile(1);

    float acc[4][8][4];
    #pragma unroll
    for (int mt = 0; mt < 4; ++mt)
        #pragma unroll
        for (int nt = 0; nt < 8; ++nt)
            #pragma unroll
            for (int j = 0; j < 4; ++j) acc[mt][nt][j] = 0.f;

    float bestv[8];
    int   besti[8];
    #pragma unroll
    for (int s = 0; s < 8; ++s) { bestv[s] = -1e30f; besti[s] = 0; }

    for (int tt = 0; tt < N_TILES; ++tt) {
        if (tt == N_TILES - 1) CP_WAIT0(); else CP_WAIT1();
        __syncthreads();

        int r24 = tt % TILES_PER_CHUNK;
        int kt  = r24 / 3;
        int sb_ = r24 % 3;
        int buf = tt & 1;
        // products: sb=0 -> sa {0,1,2}; sb=1 -> sa {0,1}; sb=2 -> sa {0}
        int sa_cnt = 3 - sb_;
        uint32_t bbase  = SB + SOFF_B  + buf * 20480 + b_off;
        uint32_t a2base = SB + SOFF_A2 + buf * 10240 + a2_off;

        #pragma unroll
        for (int km = 0; km < 2; ++km) {
            uint32_t bf[8][2];
            #pragma unroll
            for (int nt = 0; nt < 8; ++nt)
                LDSM_X2(bf[nt], bbase + nt * 640 + km * 32);
            for (int sa = 0; sa < sa_cnt; ++sa) {
                #pragma unroll
                for (int mt = 0; mt < 4; ++mt) {
                    uint32_t af[4];
                    if (sa < 2)
                        LDSM_X4(af, SB + SOFF_A + sa * 67584 + a_res_off
                                    + mt * (16 * A_STRIDE) + kt * 64 + km * 32);
                    else
                        LDSM_X4(af, a2base + mt * 1280 + km * 32);
                    #pragma unroll
                    for (int nt = 0; nt < 8; ++nt)
                        MMA16816(acc[mt][nt], af, bf[nt]);
                }
            }
        }
        __syncthreads();
        if (tt + 2 < N_TILES) issue_tile(tt + 2);

        if (r24 == TILES_PER_CHUNK - 1) {
            // ---- chunk epilogue: subtract enorm, running argmax ----
            int chunk = tt / TILES_PER_CHUNK;
            const float* ens = (const float*)(smem_raw + SOFF_ENS + (chunk & 1) * 1024);
            float ev[8][2];
            #pragma unroll
            for (int nt = 0; nt < 8; ++nt) {
                int co = warp_n * 64 + nt * 8 + (lane & 3) * 2;
                ev[nt][0] = ens[co];
                ev[nt][1] = ens[co + 1];
            }
            #pragma unroll
            for (int mt = 0; mt < 4; ++mt)
                #pragma unroll
                for (int nt = 0; nt < 8; ++nt)
                    #pragma unroll
                    for (int j = 0; j < 4; ++j) {
                        int slot = mt * 2 + (j >> 1);
                        float v = acc[mt][nt][j] - ev[nt][j & 1];
                        int code = chunk * N_CHUNK + warp_n * 64 + nt * 8 + (lane & 3) * 2 + (j & 1);
                        if (v > bestv[slot]) { bestv[slot] = v; besti[slot] = code; }
                        acc[mt][nt][j] = 0.f;
                    }
        }
    }

    // ---- final cross-thread reduction (reuse B smem) ----
    __syncthreads();
    float* redV = (float*)(smem_raw + SOFF_B);           // [128][16]
    int*   redI = (int*)(smem_raw + SOFF_B + 128 * 16 * 4);
    #pragma unroll
    for (int s = 0; s < 8; ++s) {
        int mt = s >> 1, half = s & 1;
        int row = warp_m * 64 + mt * 16 + half * 8 + (lane >> 2);
        int c16 = warp_n * 4 + (lane & 3);
        redV[row * 16 + c16] = bestv[s];
        redI[row * 16 + c16] = besti[s];
    }
    __syncthreads();
    if (tid < M_BLK) {
        float bv = redV[tid * 16];
        int   bi = redI[tid * 16];
        #pragma unroll
        for (int t = 1; t < 16; ++t) {
            float v = redV[tid * 16 + t];
            int  id = redI[tid * 16 + t];
            if (v > bv || (v == bv && id < bi)) { bv = v; bi = id; }
        }
        int n = m0 + tid;
        g_idx[n] = bi;
        dout[OFF_IDX + n] = (float)bi;
    }
}

// ---------------------------------------------------------------- epilogue kernels
__global__ void k_gather(const float* __restrict__ z, const float* __restrict__ emb,
                         float* __restrict__ dout) {
    __shared__ float sred[256];
    int t  = blockIdx.x * blockDim.x + threadIdx.x;
    int nt = gridDim.x * blockDim.x;
    float ls = 0.f;
    for (int e = t; e < TOTAL_ELEMS; e += nt) {
        int p  = e & 1023;
        int c  = (e >> 10) & 255;
        int bb = e >> 18;
        int n  = (bb << 10) + p;
        int code = g_idx[n];
        float zv = z[e];
        float ev = __ldg(emb + (size_t)code * E_DIM + c);
        dout[OFF_ZQ + e] = ev;
        float d = ev - zv;
        ls += d * d;
        atomicAdd(g_embed_sum + (size_t)code * E_DIM + c, zv);
        if (c == 0) atomicAdd(g_enc_sum + code, 1.0f);
    }
    sred[threadIdx.x] = ls;
    __syncthreads();
    for (int s = 128; s; s >>= 1) {
        if (threadIdx.x < s) sred[threadIdx.x] += sred[threadIdx.x + s];
        __syncthreads();
    }
    if (threadIdx.x == 0) atomicAdd(&g_loss, sred[0]);
}

__global__ void k_fin1(const float* __restrict__ cs, float* __restrict__ dout) {
    __shared__ float sn[1024];
    __shared__ float sp[1024];
    int t = threadIdx.x;
    float ln = 0.f, lp = 0.f;
    for (int j = t; j < N_CODES; j += 1024) {
        float es  = g_enc_sum[j];
        float ncs = cs[j] * DECAYF + OMDF * es;
        dout[OFF_CS + j] = ncs;
        ln += ncs;
        float pr = es * (1.0f / (float)N_VECS);
        lp += pr * logf(pr + 1e-10f);
    }
    sn[t] = ln; sp[t] = lp;
    __syncthreads();
    for (int s = 512; s; s >>= 1) {
        if (t < s) { sn[t] += sn[t + s]; sp[t] += sp[t + s]; }
        __syncthreads();
    }
    if (t == 0) {
        g_n = sn[0];
        dout[OFF_PERP] = expf(-sp[0]);
        dout[OFF_LOSS] = g_loss * (BETAF / (float)TOTAL_ELEMS);
    }
}

__global__ void k_fin2(const float* __restrict__ ea, float* __restrict__ dout) {
    int i = blockIdx.x * blockDim.x + threadIdx.x;
    if (i >= N_CODES * E_DIM) return;
    int code = i >> 8;
    float nea = ea[i] * DECAYF + OMDF * g_embed_sum[i];
    dout[OFF_EA + i] = nea;
    float ncs = dout[OFF_CS + code];
    float n = g_n;
    float sm = (ncs + EPSF) / (n + (float)N_CODES * EPSF) * n;
    dout[OFF_EMB + i] = nea / sm;
}

// ---------------------------------------------------------------- launch
extern "C" void kernel_launch(void* const* d_in, const int* in_sizes, int n_in,
                              void* d_out, int out_size) {
    const float* z   = (const float*)d_in[0];
    const float* emb = (const float*)d_in[1];
    const float* cs  = (const float*)d_in[2];
    const float* ea  = (const float*)d_in[3];
    float* out = (float*)d_out;

    cudaFuncSetAttribute(k_mma, cudaFuncAttributeMaxDynamicSharedMemorySize, SMEM_TOTAL);

    k_zero<<<1024, 512>>>();
    k_enorm<<<512, 256>>>(emb);
    k_split_e<<<4096, 256>>>(emb);
    k_split_z<<<dim3(32, 8, 16), dim3(32, 8)>>>(z);
    k_mma<<<N_VECS / M_BLK, 256, SMEM_TOTAL>>>(out);
    k_gather<<<4096, 256>>>(z, emb, out);
    k_fin1<<<1, 1024>>>(cs, out);
    k_fin2<<<4096, 256>>>(ea, out);
}

// round 7
// speedup vs baseline: 4.8978x; 2.3593x over previous
#include <cuda_runtime.h>
#include <cuda_bf16.h>
#include <cuda_fp16.h>
#include <math.h>
#include <stdint.h>

// ---------------------------------------------------------------- constants
#define TOTAL_ELEMS (16*256*1024)
#define N_CODES 4096
#define E_DIM   256
#define N_VECS  16384
#define DECAYF  0.99f
#define OMDF    0.01f
#define BETAF   0.25f
#define EPSF    1e-5f

#define OFF_LOSS 0
#define OFF_ZQ   1
#define OFF_PERP (1 + TOTAL_ELEMS)
#define OFF_IDX  (2 + TOTAL_ELEMS)
#define OFF_EMB  (2 + TOTAL_ELEMS + N_VECS)
#define OFF_CS   (OFF_EMB + N_CODES*E_DIM)
#define OFF_EA   (OFF_CS + N_CODES)

// Phase-1 GEMM geometry: block = 128 rows x 256-code chunks (16 chunks),
// single bf16 split (a0*b0). 8 warps, warp tile 64x64.
#define M_BLK 128
#define N_CHUNK 256
#define N_CHUNKS 16
#define TILES_PER_CHUNK 8           // 8 k-tiles of 32, one B split
#define N_TILES (N_CHUNKS * TILES_PER_CHUNK)   // 128

// smem layout (bytes from base)
#define A_STRIDE 528                // 256 bf16 = 512B + 16 pad (ldmatrix conflict-free)
#define SOFF_A    0                 // 128 x 528 = 67584
#define SOFF_B    67584             // 2 bufs x 256*80 = 40960
#define SOFF_ENS  108544            // 2 bufs x 1024
#define SMEM_TOTAL 110720

// ---------------------------------------------------------------- scratch
__device__ __align__(128) __nv_bfloat16 g_zs0[(size_t)N_VECS * E_DIM];
__device__ __align__(128) __nv_bfloat16 g_es0[(size_t)N_CODES * E_DIM];
__device__ __align__(128) float g_zfT[(size_t)N_VECS * E_DIM];   // fp32, n-major
__device__ __align__(128) __half g_scores[(size_t)N_VECS * N_CODES];
__device__ __align__(128) float g_enorm[N_CODES];
__device__ __align__(128) int   g_idx[N_VECS];
__device__ __align__(128) float g_enc_sum[N_CODES];
__device__ __align__(128) float g_embed_sum[N_CODES * E_DIM];
__device__ float g_loss;
__device__ float g_n;
__device__ float g_bmax;

// ---------------------------------------------------------------- asm helpers
__device__ __forceinline__ uint32_t smem_u32(const void* p) {
    uint32_t a;
    asm("{ .reg .u64 t; cvta.to.shared.u64 t, %1; cvt.u32.u64 %0, t; }" : "=r"(a) : "l"(p));
    return a;
}
#define CP16(dst, src)   asm volatile("cp.async.cg.shared.global [%0], [%1], 16;" :: "r"(dst), "l"(src) : "memory")
#define CP_COMMIT()      asm volatile("cp.async.commit_group;" ::: "memory")
#define CP_WAIT1()       asm volatile("cp.async.wait_group 1;" ::: "memory")
#define CP_WAIT0()       asm volatile("cp.async.wait_group 0;" ::: "memory")

#define LDSM_X4(r, addr) asm volatile( \
    "ldmatrix.sync.aligned.m8n8.x4.shared.b16 {%0,%1,%2,%3}, [%4];" \
    : "=r"((r)[0]),"=r"((r)[1]),"=r"((r)[2]),"=r"((r)[3]) : "r"(addr))
#define LDSM_X2(r, addr) asm volatile( \
    "ldmatrix.sync.aligned.m8n8.x2.shared.b16 {%0,%1}, [%2];" \
    : "=r"((r)[0]),"=r"((r)[1]) : "r"(addr))

#define MMA16816(c, a, b) asm volatile( \
    "mma.sync.aligned.m16n8k16.row.col.f32.bf16.bf16.f32 " \
    "{%0,%1,%2,%3}, {%4,%5,%6,%7}, {%8,%9}, {%0,%1,%2,%3};" \
    : "+f"((c)[0]),"+f"((c)[1]),"+f"((c)[2]),"+f"((c)[3]) \
    : "r"((a)[0]),"r"((a)[1]),"r"((a)[2]),"r"((a)[3]), "r"((b)[0]),"r"((b)[1]))

// ---------------------------------------------------------------- prep kernels
__global__ void k_zero() {
    int t = blockIdx.x * blockDim.x + threadIdx.x;
    int nt = gridDim.x * blockDim.x;
    for (int i = t; i < N_CODES * E_DIM; i += nt) g_embed_sum[i] = 0.f;
    for (int i = t; i < N_CODES; i += nt) g_enc_sum[i] = 0.f;
    if (t == 0) { g_loss = 0.f; g_bmax = 0.f; }
}

__global__ void k_enorm(const float* __restrict__ emb) {
    int warp = (blockIdx.x * blockDim.x + threadIdx.x) >> 5;
    int lane = threadIdx.x & 31;
    if (warp >= N_CODES) return;
    const float* r = emb + warp * E_DIM;
    float s = 0.f;
    #pragma unroll
    for (int c = 0; c < E_DIM; c += 32) { float v = r[c + lane]; s += v * v; }
    #pragma unroll
    for (int o = 16; o; o >>= 1) s += __shfl_down_sync(0xffffffffu, s, o);
    if (lane == 0) {
        g_enorm[warp] = 0.5f * s;
        atomicMax((int*)&g_bmax, __float_as_int(sqrtf(s)));   // positive floats
    }
}

// z (b, c, p) -> g_zs0 bf16 and g_zfT fp32, both [n = b*1024+p][k = c]
__global__ void k_split_z(const float* __restrict__ z) {
    __shared__ float t[32][33];
    int b  = blockIdx.z;
    int c0 = blockIdx.y * 32;
    int p0 = blockIdx.x * 32;
    #pragma unroll
    for (int i = 0; i < 32; i += 8)
        t[threadIdx.y + i][threadIdx.x] =
            z[((size_t)(b * 256 + c0 + threadIdx.y + i)) * 1024 + p0 + threadIdx.x];
    __syncthreads();
    #pragma unroll
    for (int i = 0; i < 32; i += 8) {
        int n = b * 1024 + p0 + threadIdx.y + i;
        int k = c0 + threadIdx.x;
        float v = t[threadIdx.x][threadIdx.y + i];
        size_t o = (size_t)n * E_DIM + k;
        g_zs0[o] = __float2bfloat16(v);
        g_zfT[o] = v;
    }
}

__global__ void k_split_e(const float* __restrict__ emb) {
    int i = blockIdx.x * blockDim.x + threadIdx.x;
    if (i >= N_CODES * E_DIM) return;
    g_es0[i] = __float2bfloat16(emb[i]);
}

// ---------------------------------------------------------------- phase 1: approx GEMM
__global__ __launch_bounds__(256) void k_mma(float* __restrict__ dout) {
    extern __shared__ char smem_raw[];
    const uint32_t SB = smem_u32(smem_raw);
    const int tid  = threadIdx.x;
    const int lane = tid & 31;
    const int wid  = tid >> 5;
    const int warp_m = wid >> 2;        // 0..1
    const int warp_n = wid & 3;         // 0..3
    const int m0 = blockIdx.x * M_BLK;

    const int a_row = warp_m * 64 + ((lane >> 3) & 1) * 8 + (lane & 7);
    const uint32_t a_res_off = (uint32_t)(a_row * A_STRIDE + ((lane >> 4) & 1) * 16);
    const int lb = lane & 15;
    const uint32_t b_off = (uint32_t)((warp_n * 64 + (lb & 7)) * 80 + ((lb >> 3) & 1) * 16);

    // tile tt: chunk = tt>>3, kt = tt&7, buf = tt&1
    auto issue_tile = [&](int tt) {
        int kt    = tt & 7;
        int chunk = tt >> 3;
        int buf   = tt & 1;
        #pragma unroll
        for (int i = 0; i < 4; ++i) {
            int li = tid + i * 256;          // 0..1023
            int code = li >> 2, seg = li & 3;
            const char* src = (const char*)(g_es0
                + (size_t)(chunk * N_CHUNK + code) * E_DIM + kt * 32 + seg * 8);
            CP16(SB + SOFF_B + buf * 20480 + code * 80 + seg * 16, src);
        }
        if (kt == 0 && tid < 64) {           // ens for this chunk
            const char* src = (const char*)(g_enorm + chunk * N_CHUNK + tid * 4);
            CP16(SB + SOFF_ENS + (chunk & 1) * 1024 + tid * 16, src);
        }
        CP_COMMIT();
    };

    // A panel (split 0) resident
    #pragma unroll
    for (int i = 0; i < 16; ++i) {
        int li = tid + i * 256;              // 0..4095
        int row = li >> 5, seg = li & 31;
        const char* src = (const char*)(g_zs0 + (size_t)(m0 + row) * E_DIM + seg * 8);
        CP16(SB + SOFF_A + row * A_STRIDE + seg * 16, src);
    }
    CP_COMMIT();
    issue_tile(0);
    issue_tile(1);

    float acc[4][8][4];
    #pragma unroll
    for (int mt = 0; mt < 4; ++mt)
        #pragma unroll
        for (int nt = 0; nt < 8; ++nt)
            #pragma unroll
            for (int j = 0; j < 4; ++j) acc[mt][nt][j] = 0.f;

    for (int tt = 0; tt < N_TILES; ++tt) {
        if (tt == N_TILES - 1) CP_WAIT0(); else CP_WAIT1();
        __syncthreads();

        int kt  = tt & 7;
        int buf = tt & 1;
        uint32_t bbase = SB + SOFF_B + buf * 20480 + b_off;

        #pragma unroll
        for (int km = 0; km < 2; ++km) {
            uint32_t bf[8][2];
            #pragma unroll
            for (int nt = 0; nt < 8; ++nt)
                LDSM_X2(bf[nt], bbase + nt * 640 + km * 32);
            #pragma unroll
            for (int mt = 0; mt < 4; ++mt) {
                uint32_t af[4];
                LDSM_X4(af, SB + SOFF_A + a_res_off
                            + mt * (16 * A_STRIDE) + kt * 64 + km * 32);
                #pragma unroll
                for (int nt = 0; nt < 8; ++nt)
                    MMA16816(acc[mt][nt], af, bf[nt]);
            }
        }
        __syncthreads();
        if (tt + 2 < N_TILES) issue_tile(tt + 2);

        if (kt == 7) {
            // ---- chunk epilogue: subtract enorm, store fp16 scores ----
            int chunk = tt >> 3;
            const float* ens = (const float*)(smem_raw + SOFF_ENS + (chunk & 1) * 1024);
            #pragma unroll
            for (int mt = 0; mt < 4; ++mt) {
                int row = m0 + warp_m * 64 + mt * 16 + (lane >> 2);
                #pragma unroll
                for (int nt = 0; nt < 8; ++nt) {
                    int cl = warp_n * 64 + nt * 8 + (lane & 3) * 2;  // col in chunk
                    int col = chunk * N_CHUNK + cl;
                    __half2 h0 = __floats2half2_rn(acc[mt][nt][0] - ens[cl],
                                                   acc[mt][nt][1] - ens[cl + 1]);
                    __half2 h1 = __floats2half2_rn(acc[mt][nt][2] - ens[cl],
                                                   acc[mt][nt][3] - ens[cl + 1]);
                    *(__half2*)(g_scores + (size_t)row * N_CODES + col) = h0;
                    *(__half2*)(g_scores + (size_t)(row + 8) * N_CODES + col) = h1;
                    acc[mt][nt][0] = 0.f; acc[mt][nt][1] = 0.f;
                    acc[mt][nt][2] = 0.f; acc[mt][nt][3] = 0.f;
                }
            }
        }
    }
    (void)dout;
}

// ---------------------------------------------------------------- phase 2: exact rescore
// Warp per row. Rigorous candidate margin: |s_true - s_approx| <=
// 2u*||z||*||e||max (+half-store +slack), u = 2^-8 (bf16 RN). Exact fp32
// rescore of all candidates, first-min tie rule on ascending code order.
__global__ __launch_bounds__(256) void k_refine(const float* __restrict__ emb,
                                                float* __restrict__ dout) {
    int w = threadIdx.x >> 5;
    int lane = threadIdx.x & 31;
    int n = blockIdx.x * 8 + w;
    if (n >= N_VECS) return;

    // z row (fp32, coalesced)
    float zr[8];
    float an2 = 0.f;
    #pragma unroll
    for (int j = 0; j < 8; ++j) {
        zr[j] = g_zfT[(size_t)n * E_DIM + lane + 32 * j];
        an2 += zr[j] * zr[j];
    }
    #pragma unroll
    for (int o = 16; o; o >>= 1) an2 += __shfl_xor_sync(0xffffffffu, an2, o);

    const __half2* sr = (const __half2*)(g_scores + (size_t)n * N_CODES);

    // pass 1: max of approx scores
    float mx = -1e30f;
    #pragma unroll 8
    for (int i = 0; i < 64; ++i) {
        float2 v = __half22float2(sr[i * 32 + lane]);
        mx = fmaxf(mx, fmaxf(v.x, v.y));
    }
    #pragma unroll
    for (int o = 16; o; o >>= 1) mx = fmaxf(mx, __shfl_xor_sync(0xffffffffu, mx, o));

    // margin: 2 * (2.01*2^-8 * ||z|| * bmax) + half-store err + slack
    float margin = 0.0158f * sqrtf(an2) * g_bmax + 1.2f;
    float thr = mx - margin;

    float best_v = -1e30f;
    int   best_i = 0x7fffffff;

    for (int i = 0; i < 64; ++i) {
        float2 v = __half22float2(sr[i * 32 + lane]);
        unsigned m0 = __ballot_sync(0xffffffffu, v.x >= thr);
        unsigned m1 = __ballot_sync(0xffffffffu, v.y >= thr);
        unsigned mm = m0 | m1;
        while (mm) {
            int l = __ffs(mm) - 1;
            mm &= mm - 1;
            #pragma unroll
            for (int e = 0; e < 2; ++e) {
                if (!((e ? m1 : m0) >> l & 1)) continue;
                int c = i * 64 + l * 2 + e;
                // exact fp32 dot (coalesced e row)
                const float* er = emb + (size_t)c * E_DIM;
                float d = 0.f;
                #pragma unroll
                for (int j = 0; j < 8; ++j)
                    d = fmaf(zr[j], er[lane + 32 * j], d);
                #pragma unroll
                for (int o = 16; o; o >>= 1) d += __shfl_xor_sync(0xffffffffu, d, o);
                float sv = d - g_enorm[c];
                if (sv > best_v || (sv == best_v && c < best_i)) { best_v = sv; best_i = c; }
            }
        }
    }
    if (lane == 0) {
        g_idx[n] = best_i;
        dout[OFF_IDX + n] = (float)best_i;
    }
}

// ---------------------------------------------------------------- epilogue kernels
__global__ void k_gather(const float* __restrict__ z, const float* __restrict__ emb,
                         float* __restrict__ dout) {
    __shared__ float sred[256];
    int t  = blockIdx.x * blockDim.x + threadIdx.x;
    int nt = gridDim.x * blockDim.x;
    float ls = 0.f;
    for (int e = t; e < TOTAL_ELEMS; e += nt) {
        int p  = e & 1023;
        int c  = (e >> 10) & 255;
        int bb = e >> 18;
        int n  = (bb << 10) + p;
        int code = g_idx[n];
        float zv = z[e];
        float ev = __ldg(emb + (size_t)code * E_DIM + c);
        dout[OFF_ZQ + e] = ev;
        float d = ev - zv;
        ls += d * d;
        atomicAdd(g_embed_sum + (size_t)code * E_DIM + c, zv);
        if (c == 0) atomicAdd(g_enc_sum + code, 1.0f);
    }
    sred[threadIdx.x] = ls;
    __syncthreads();
    for (int s = 128; s; s >>= 1) {
        if (threadIdx.x < s) sred[threadIdx.x] += sred[threadIdx.x + s];
        __syncthreads();
    }
    if (threadIdx.x == 0) atomicAdd(&g_loss, sred[0]);
}

__global__ void k_fin1(const float* __restrict__ cs, float* __restrict__ dout) {
    __shared__ float sn[1024];
    __shared__ float sp[1024];
    int t = threadIdx.x;
    float ln = 0.f, lp = 0.f;
    for (int j = t; j < N_CODES; j += 1024) {
        float es  = g_enc_sum[j];
        float ncs = cs[j] * DECAYF + OMDF * es;
        dout[OFF_CS + j] = ncs;
        ln += ncs;
        float pr = es * (1.0f / (float)N_VECS);
        lp += pr * logf(pr + 1e-10f);
    }
    sn[t] = ln; sp[t] = lp;
    __syncthreads();
    for (int s = 512; s; s >>= 1) {
        if (t < s) { sn[t] += sn[t + s]; sp[t] += sp[t + s]; }
        __syncthreads();
    }
    if (t == 0) {
        g_n = sn[0];
        dout[OFF_PERP] = expf(-sp[0]);
        dout[OFF_LOSS] = g_loss * (BETAF / (float)TOTAL_ELEMS);
    }
}

__global__ void k_fin2(const float* __restrict__ ea, float* __restrict__ dout) {
    int i = blockIdx.x * blockDim.x + threadIdx.x;
    if (i >= N_CODES * E_DIM) return;
    int code = i >> 8;
    float nea = ea[i] * DECAYF + OMDF * g_embed_sum[i];
    dout[OFF_EA + i] = nea;
    float ncs = dout[OFF_CS + code];
    float n = g_n;
    float sm = (ncs + EPSF) / (n + (float)N_CODES * EPSF) * n;
    dout[OFF_EMB + i] = nea / sm;
}

// ---------------------------------------------------------------- launch
extern "C" void kernel_launch(void* const* d_in, const int* in_sizes, int n_in,
                              void* d_out, int out_size) {
    const float* z   = (const float*)d_in[0];
    const float* emb = (const float*)d_in[1];
    const float* cs  = (const float*)d_in[2];
    const float* ea  = (const float*)d_in[3];
    float* out = (float*)d_out;

    cudaFuncSetAttribute(k_mma, cudaFuncAttributeMaxDynamicSharedMemorySize, SMEM_TOTAL);

    k_zero<<<1024, 512>>>();
    k_enorm<<<512, 256>>>(emb);
    k_split_e<<<4096, 256>>>(emb);
    k_split_z<<<dim3(32, 8, 16), dim3(32, 8)>>>(z);
    k_mma<<<N_VECS / M_BLK, 256, SMEM_TOTAL>>>(out);
    k_refine<<<N_VECS / 8, 256>>>(emb, out);
    k_gather<<<4096, 256>>>(z, emb, out);
    k_fin1<<<1, 1024>>>(cs, out);
    k_fin2<<<4096, 256>>>(ea, out);
}